// round 10
// baseline (speedup 1.0000x reference)
#include <cuda_runtime.h>
#include <math.h>

// ---- problem constants ----
#define NBATCH 4
#define NATOMS 600
#define NPAD   640
#define NBINS  64
#define BIN_W      0.1171875f            // 7.5/64 (exact fp32)
#define CUT_ADJ    7.734375f             // 7.5 + 2*BIN_W (exact)
#define GW         (7.5f / 63.0f)
#define GCOEFF     (-0.5f / (GW * GW))

// fine sub-histogram: 1024 bins, (count, moment) packed into one u64
#define NSUB       1024
#define SUBW       (CUT_ADJ / (float)NSUB)
#define INV_SUBW   ((float)NSUB / CUT_ADJ)
#define FIX        4194304.0f            // 2^22 fixed point for the moment
#define INV_FIX    (1.0f / 4194304.0f)
#define MBIAS      32768

// finalize window: 192 sub-bins (+-6.1 Gaussian widths), zero guards
#define PAD        96
#define SEG_LEN    12                    // 16 threads per final bin

// 2 CTAs/SM: 296 blocks x 1024 threads = 64 warps/SM (occ ~100%)
#define TPB        1024
#define WPB        32
#define BPB        74                    // blocks per batch
#define A_BLOCKS   (BPB * NBATCH)        // 296
#define IGRP       20                    // i-groups of 32 (640 padded atoms)
#define JLEN       5
#define NJC        120                   // j-chunks of 5 (covers [0,600))
#define TASKS      (IGRP * NJC)          // 2400 warp-tasks per batch
#define WARPS_PB   (BPB * WPB)           // 2368 warps per batch
#define EXTRA      (TASKS - WARPS_PB)    // 32 leftover tasks -> warps 0..31

// static device scratch (zeroed at load; re-zeroed by finalize block each call)
__device__ unsigned long long g_pk[NSUB];
__device__ unsigned int       g_done = 0;

__device__ __forceinline__ void do_task(
    const float4* __restrict__ s_pos, unsigned long long* __restrict__ s_pk,
    int ig, int jc, int lane)
{
    const float cut2 = CUT_ADJ * CUT_ADJ;
    const float4 pi = s_pos[ig * 32 + lane];
    const int j0 = jc * JLEN;
    #pragma unroll
    for (int jj = 0; jj < JLEN; ++jj) {
        float4 pj = s_pos[j0 + jj];       // warp-uniform -> LDS broadcast
        float ax = fabsf(pj.x - pi.x);
        float ay = fabsf(pj.y - pi.y);
        float az = fabsf(pj.z - pi.z);
        float mx = fminf(ax, 20.0f - ax);
        float my = fminf(ay, 20.0f - ay);
        float mz = fminf(az, 20.0f - az);
        float ds = fmaf(mx, mx, fmaf(my, my, mz * mz));
        if (ds > 0.0f && ds < cut2) {     // NaN (pad atoms) fails both
            float d = ds * rsqrtf(ds);
            int s = (int)(d * INV_SUBW);
            if (s > NSUB - 1) s = NSUB - 1;
            float cs = ((float)s + 0.5f) * SUBW;
            int mq = __float2int_rn((d - cs) * FIX);
            unsigned long long pk =
                (1ull << 32) | (unsigned long long)(unsigned)(mq + MBIAS);
            atomicAdd(&s_pk[s], pk);
        }
    }
}

__global__ void __launch_bounds__(TPB, 2)
rdf_fused_kernel(const float* __restrict__ xyz, float* __restrict__ out, int out_size) {
    __shared__ float4             s_pos[NPAD];          // 10.24 KB
    __shared__ unsigned long long s_pk[NSUB];           // 8 KB
    __shared__ float              s_nf[NSUB + 2 * PAD];
    __shared__ float              s_mf[NSUB + 2 * PAD];
    __shared__ float              s_cnt[NBINS];
    __shared__ float              s_total;
    __shared__ int                s_last;

    const int t    = threadIdx.x;
    const int lane = t & 31;
    const int w    = t >> 5;
    const int bat  = blockIdx.x / BPB;
    const int remb = blockIdx.x - bat * BPB;

    // stage this batch's positions (single round, 1024 threads)
    const float* __restrict__ src = xyz + bat * NATOMS * 3;
    if (t < NPAD) {
        const float qnan = __int_as_float(0x7fffffff);
        float4 p;
        if (t < NATOMS) p = make_float4(src[3 * t], src[3 * t + 1], src[3 * t + 2], 0.0f);
        else            p = make_float4(qnan, qnan, qnan, 0.0f);
        s_pos[t] = p;
    }
    s_pk[t] = 0ull;
    __syncthreads();

    // warp-task within batch
    const int wb = remb * WPB + w;        // 0..2367
    {
        const int jc = wb / IGRP;
        const int ig = wb - jc * IGRP;
        do_task(s_pos, s_pk, ig, jc, lane);
    }
    if (wb < EXTRA) {                     // leftover tasks 2368..2399
        const int t2 = WARPS_PB + wb;
        const int jc = t2 / IGRP;
        const int ig = t2 - jc * IGRP;
        do_task(s_pos, s_pk, ig, jc, lane);
    }
    __syncthreads();

    // flush: one sub-bin per thread, skip empties
    {
        unsigned long long pv = s_pk[t];
        if (pv) atomicAdd(&g_pk[t], pv);
    }
    __threadfence();
    __syncthreads();
    if (t == 0) {
        unsigned int old = atomicAdd(&g_done, 1u);
        s_last = (old == A_BLOCKS - 1);
    }
    __syncthreads();
    if (!s_last) return;

    // ================= last block: reconstruction + finalize =================
    __threadfence();

    if (t < NSUB + 2 * PAD) { s_nf[t] = 0.0f; s_mf[t] = 0.0f; }
    __syncthreads();
    {
        unsigned long long pv = g_pk[t];
        g_pk[t] = 0ull;                   // reset for next graph replay
        float n = (float)(unsigned)(pv >> 32);
        float m = ((float)(int)((unsigned)pv - (unsigned)(pv >> 32) * MBIAS)) * INV_FIX;
        s_nf[PAD + t] = n;
        s_mf[PAD + t] = m;
    }
    __syncthreads();

    // final bin k: 16 threads x 12 fixed-trip sub-bins; exp recurrence
    {
        const int k   = t >> 4;           // 0..63
        const int seg = t & 15;
        const float ck = (float)k * GW;
        const int s0 = __float2int_rn(ck * INV_SUBW) - 96 + seg * SEG_LEN;

        const float dlt = SUBW;
        float uu = ((float)s0 + 0.5f) * SUBW - ck;
        float e  = __expf(GCOEFF * uu * uu);
        float tt = __expf(GCOEFF * fmaf(2.0f * uu, dlt, dlt * dlt));
        const float q = __expf(2.0f * GCOEFF * dlt * dlt);

        float acc = 0.0f;
        #pragma unroll
        for (int ii = 0; ii < SEG_LEN; ++ii) {
            float n = s_nf[PAD + s0 + ii];
            float m = s_mf[PAD + s0 + ii];
            acc = fmaf(e, fmaf(2.0f * GCOEFF * uu, m, n), acc);  // n*f + m*f'
            e *= tt;
            tt *= q;
            uu += dlt;
        }
        acc += __shfl_xor_sync(0xffffffffu, acc, 1);
        acc += __shfl_xor_sync(0xffffffffu, acc, 2);
        acc += __shfl_xor_sync(0xffffffffu, acc, 4);
        acc += __shfl_xor_sync(0xffffffffu, acc, 8);
        if (seg == 0) s_cnt[k] = acc;
    }
    __syncthreads();
    if (t == 0) {
        float sum = 0.0f;
        for (int k = 0; k < NBINS; ++k) sum += s_cnt[k];
        s_total = sum;
        g_done = 0;
    }
    __syncthreads();

    const float pi43 = 4.0f * 3.14159265358979f / 3.0f;
    const float num  = (2.0f * CUT_ADJ) * (2.0f * CUT_ADJ) * (2.0f * CUT_ADJ);
    if (out_size >= 2 * NBINS + 1) {
        // layout: BINS[65] then rdf[64]
        if (t <= NBINS) out[t] = (float)t * BIN_W;
        if (t < NBINS) {
            float b0 = (float)t * BIN_W;
            float b1 = (float)(t + 1) * BIN_W;
            float vol = pi43 * (b1 * b1 * b1 - b0 * b0 * b0);
            out[NBINS + 1 + t] = (s_cnt[t] / s_total) * num / (2.0f * vol);
        }
    } else {
        if (t < NBINS && t < out_size) {
            float b0 = (float)t * BIN_W;
            float b1 = (float)(t + 1) * BIN_W;
            float vol = pi43 * (b1 * b1 * b1 - b0 * b0 * b0);
            out[t] = (s_cnt[t] / s_total) * num / (2.0f * vol);
        }
    }
}

extern "C" void kernel_launch(void* const* d_in, const int* in_sizes, int n_in,
                              void* d_out, int out_size) {
    const float* xyz = (const float*)d_in[0];
    float* out = (float*)d_out;
    rdf_fused_kernel<<<A_BLOCKS, TPB>>>(xyz, out, out_size);
}

// round 11
// speedup vs baseline: 1.1716x; 1.1716x over previous
#include <cuda_runtime.h>
#include <math.h>

// ---- problem constants ----
#define NBATCH 4
#define NATOMS 600
#define NPAD   640
#define NBINS  64
#define BIN_W      0.1171875f            // 7.5/64 (exact fp32)
#define CUT_ADJ    7.734375f             // 7.5 + 2*BIN_W (exact)
#define GW         (7.5f / 63.0f)
#define GCOEFF     (-0.5f / (GW * GW))

// fine sub-histogram: 1024 bins, (count, moment) packed into one u64
#define NSUB       1024
#define SUBW       (CUT_ADJ / (float)NSUB)
#define INV_SUBW   ((float)NSUB / CUT_ADJ)
#define FIX        4194304.0f            // 2^22 fixed point for the moment
#define INV_FIX    (1.0f / 4194304.0f)
#define MBIAS      32768

// finalize window: 192 sub-bins (+-6.1 Gaussian widths), zero guards
#define PAD        96
#define SEG_LEN    12                    // 16 threads per final bin

// 148 fat blocks (1/SM, one wave), 1024 threads
#define TPB        1024
#define WPB        32
#define BPB        37                    // blocks per batch
#define A_BLOCKS   (BPB * NBATCH)        // 148
#define IGRP       20                    // i-groups of 32
#define JLEN       10
#define NJC        60                    // j-chunks of 10
#define NTASK      600                   // upper-triangle tiles per batch

// static device scratch (zeroed at load; re-zeroed by finalize block each call)
__device__ unsigned long long g_pk[NSUB];
__device__ unsigned int       g_done = 0;

// kept tiles per j-chunk (upper triangle): ig allowed in [0, KEPT(jc))
#define KEPT(q) ((10 * (q) + 8) / 32 + 1)

__global__ void __launch_bounds__(TPB, 1)
rdf_fused_kernel(const float* __restrict__ xyz, float* __restrict__ out, int out_size) {
    __shared__ float4             s_pos[NPAD];          // 10.24 KB
    __shared__ unsigned long long s_pk[NSUB];           // 8 KB
    __shared__ float              s_nf[NSUB + 2 * PAD];
    __shared__ float              s_mf[NSUB + 2 * PAD];
    __shared__ float              s_cnt[NBINS];
    __shared__ float              s_total;
    __shared__ int                s_last;

    const int t    = threadIdx.x;
    const int lane = t & 31;
    const int w    = t >> 5;
    const int bat  = blockIdx.x / BPB;
    const int remb = blockIdx.x - bat * BPB;

    // stage this batch's positions (single round; NaN tail rejects pad atoms)
    const float* __restrict__ src = xyz + bat * NATOMS * 3;
    if (t < NPAD) {
        const float qnan = __int_as_float(0x7fffffff);
        float4 p;
        if (t < NATOMS) p = make_float4(src[3 * t], src[3 * t + 1], src[3 * t + 2], 0.0f);
        else            p = make_float4(qnan, qnan, qnan, 0.0f);
        s_pos[t] = p;
    }
    s_pk[t] = 0ull;
    __syncthreads();

    // ---- balanced upper-triangle task assignment ----
    // task tau = w*BPB + remb, active iff tau < NTASK -> 16-17 tasks per block.
    const int tau = w * BPB + remb;
    if (tau < NTASK) {
        // tau -> (jc, ig): prefix scan over compile-time kept(jc) counts
        int jc = 0, base = 0;
        #pragma unroll
        for (int q = 0; q < NJC - 1; ++q) {
            const int k = KEPT(q);        // compile-time constant per q
            if (tau >= base + k) { base += k; jc = q + 1; }
        }
        const int ig = tau - base;

        const int i = ig * 32 + lane;
        const float4 pi = s_pos[i];
        const int j0 = jc * JLEN;
        const float cut2 = CUT_ADJ * CUT_ADJ;

        #pragma unroll
        for (int jj = 0; jj < JLEN; ++jj) {
            const int j = j0 + jj;
            float4 pj = s_pos[j];         // warp-uniform -> LDS broadcast
            float ax = fabsf(pj.x - pi.x);
            float ay = fabsf(pj.y - pi.y);
            float az = fabsf(pj.z - pi.z);
            float mx = fminf(ax, 20.0f - ax);
            float my = fminf(ay, 20.0f - ay);
            float mz = fminf(az, 20.0f - az);
            float ds = fmaf(mx, mx, fmaf(my, my, mz * mz));
            // unordered pairs only (count scales by exactly 1/2 -> rdf invariant);
            // NaN pad atoms fail ds < cut2
            if (j > i && ds < cut2) {
                float d = ds * rsqrtf(ds);
                int s = (int)(d * INV_SUBW);
                if (s > NSUB - 1) s = NSUB - 1;
                float cs = ((float)s + 0.5f) * SUBW;
                int mq = __float2int_rn((d - cs) * FIX);
                unsigned long long pk =
                    (1ull << 32) | (unsigned long long)(unsigned)(mq + MBIAS);
                atomicAdd(&s_pk[s], pk);
            }
        }
    }
    __syncthreads();

    // flush: one sub-bin per thread, skip empties
    {
        unsigned long long pv = s_pk[t];
        if (pv) atomicAdd(&g_pk[t], pv);
    }
    __threadfence();
    __syncthreads();
    if (t == 0) {
        unsigned int old = atomicAdd(&g_done, 1u);
        s_last = (old == A_BLOCKS - 1);
    }
    __syncthreads();
    if (!s_last) return;

    // ================= last block: reconstruction + finalize =================
    __threadfence();

    if (t < NSUB + 2 * PAD) { s_nf[t] = 0.0f; s_mf[t] = 0.0f; }
    __syncthreads();
    {
        unsigned long long pv = g_pk[t];
        g_pk[t] = 0ull;                   // reset for next graph replay
        float n = (float)(unsigned)(pv >> 32);
        float m = ((float)(int)((unsigned)pv - (unsigned)(pv >> 32) * MBIAS)) * INV_FIX;
        s_nf[PAD + t] = n;
        s_mf[PAD + t] = m;
    }
    __syncthreads();

    // final bin k: 16 threads x 12 fixed-trip sub-bins; exp recurrence
    {
        const int k   = t >> 4;           // 0..63
        const int seg = t & 15;
        const float ck = (float)k * GW;
        const int s0 = __float2int_rn(ck * INV_SUBW) - 96 + seg * SEG_LEN;

        const float dlt = SUBW;
        float uu = ((float)s0 + 0.5f) * SUBW - ck;
        float e  = __expf(GCOEFF * uu * uu);
        float tt = __expf(GCOEFF * fmaf(2.0f * uu, dlt, dlt * dlt));
        const float q = __expf(2.0f * GCOEFF * dlt * dlt);

        float acc = 0.0f;
        #pragma unroll
        for (int ii = 0; ii < SEG_LEN; ++ii) {
            float n = s_nf[PAD + s0 + ii];
            float m = s_mf[PAD + s0 + ii];
            acc = fmaf(e, fmaf(2.0f * GCOEFF * uu, m, n), acc);  // n*f + m*f'
            e *= tt;
            tt *= q;
            uu += dlt;
        }
        acc += __shfl_xor_sync(0xffffffffu, acc, 1);
        acc += __shfl_xor_sync(0xffffffffu, acc, 2);
        acc += __shfl_xor_sync(0xffffffffu, acc, 4);
        acc += __shfl_xor_sync(0xffffffffu, acc, 8);
        if (seg == 0) s_cnt[k] = acc;
    }
    __syncthreads();
    if (t == 0) {
        float sum = 0.0f;
        for (int k = 0; k < NBINS; ++k) sum += s_cnt[k];
        s_total = sum;
        g_done = 0;
    }
    __syncthreads();

    const float pi43 = 4.0f * 3.14159265358979f / 3.0f;
    const float num  = (2.0f * CUT_ADJ) * (2.0f * CUT_ADJ) * (2.0f * CUT_ADJ);
    if (out_size >= 2 * NBINS + 1) {
        // layout: BINS[65] then rdf[64]
        if (t <= NBINS) out[t] = (float)t * BIN_W;
        if (t < NBINS) {
            float b0 = (float)t * BIN_W;
            float b1 = (float)(t + 1) * BIN_W;
            float vol = pi43 * (b1 * b1 * b1 - b0 * b0 * b0);
            out[NBINS + 1 + t] = (s_cnt[t] / s_total) * num / (2.0f * vol);
        }
    } else {
        if (t < NBINS && t < out_size) {
            float b0 = (float)t * BIN_W;
            float b1 = (float)(t + 1) * BIN_W;
            float vol = pi43 * (b1 * b1 * b1 - b0 * b0 * b0);
            out[t] = (s_cnt[t] / s_total) * num / (2.0f * vol);
        }
    }
}

extern "C" void kernel_launch(void* const* d_in, const int* in_sizes, int n_in,
                              void* d_out, int out_size) {
    const float* xyz = (const float*)d_in[0];
    float* out = (float*)d_out;
    rdf_fused_kernel<<<A_BLOCKS, TPB>>>(xyz, out, out_size);
}

// round 13
// speedup vs baseline: 1.1775x; 1.0050x over previous
#include <cuda_runtime.h>
#include <math.h>

// ---- problem constants ----
#define NBATCH 4
#define NATOMS 600
#define NPAD   640
#define NBINS  64
#define BIN_W      0.1171875f            // 7.5/64 (exact fp32)
#define CUT_ADJ    7.734375f             // 7.5 + 2*BIN_W (exact)
#define GW         (7.5f / 63.0f)
#define GCOEFF     (-0.5f / (GW * GW))

// fine sub-histogram: 1024 bins, (count, moment) packed into one u64
#define NSUB       1024
#define SUBW       (CUT_ADJ / (float)NSUB)
#define INV_SUBW   ((float)NSUB / CUT_ADJ)
#define FIX        4194304.0f            // 2^22 fixed point for the moment
#define INV_FIX    (1.0f / 4194304.0f)
#define MBIAS      32768

// finalize window: 192 sub-bins (+-6.1 Gaussian widths), zero guards
#define PAD        96
#define SEG_LEN    12                    // 16 threads per final bin

// K1: 148 fat blocks (1/SM, one wave), 1024 threads
#define TPB        1024
#define WPB        32
#define BPB        37                    // blocks per batch
#define A_BLOCKS   (BPB * NBATCH)        // 148
#define IGRP       20                    // i-groups of 32
#define JLEN       10
#define NJC        60                    // j-chunks of 10
#define NTASK      600                   // upper-triangle tiles per batch

// static device scratch (zeroed at load; re-zeroed by K2 every call)
__device__ unsigned long long g_pk[NSUB];

// kept tiles per j-chunk (upper triangle): ig allowed in [0, KEPT(jc))
#define KEPT(q) ((10 * (q) + 8) / 32 + 1)

// =================== K1: pairs -> global packed sub-histogram ===================
__global__ void __launch_bounds__(TPB, 1)
rdf_pairs_kernel(const float* __restrict__ xyz) {
    __shared__ float4             s_pos[NPAD];          // 10.24 KB
    __shared__ unsigned long long s_pk[NSUB];           // 8 KB

    const int t    = threadIdx.x;
    const int lane = t & 31;
    const int w    = t >> 5;
    const int bat  = blockIdx.x / BPB;
    const int remb = blockIdx.x - bat * BPB;

    // stage this batch's positions (single round; NaN tail rejects pad atoms)
    const float* __restrict__ src = xyz + bat * NATOMS * 3;
    if (t < NPAD) {
        const float qnan = __int_as_float(0x7fffffff);
        float4 p;
        if (t < NATOMS) p = make_float4(src[3 * t], src[3 * t + 1], src[3 * t + 2], 0.0f);
        else            p = make_float4(qnan, qnan, qnan, 0.0f);
        s_pos[t] = p;
    }
    s_pk[t] = 0ull;
    __syncthreads();

    // balanced upper-triangle task assignment: tau = w*BPB + remb < NTASK
    const int tau = w * BPB + remb;
    if (tau < NTASK) {
        int jc = 0, base = 0;
        #pragma unroll
        for (int q = 0; q < NJC - 1; ++q) {
            const int k = KEPT(q);        // compile-time constant
            if (tau >= base + k) { base += k; jc = q + 1; }
        }
        const int ig = tau - base;

        const int i = ig * 32 + lane;
        const float4 pi = s_pos[i];
        const int j0 = jc * JLEN;
        const float cut2 = CUT_ADJ * CUT_ADJ;

        #pragma unroll
        for (int jj = 0; jj < JLEN; ++jj) {
            const int j = j0 + jj;
            float4 pj = s_pos[j];         // warp-uniform -> LDS broadcast
            float ax = fabsf(pj.x - pi.x);
            float ay = fabsf(pj.y - pi.y);
            float az = fabsf(pj.z - pi.z);
            float mx = fminf(ax, 20.0f - ax);
            float my = fminf(ay, 20.0f - ay);
            float mz = fminf(az, 20.0f - az);
            float ds = fmaf(mx, mx, fmaf(my, my, mz * mz));
            // unordered pairs (count scales by 1/2 exactly -> rdf invariant);
            // NaN pad atoms fail ds < cut2
            if (j > i && ds < cut2) {
                float d = ds * rsqrtf(ds);
                int s = (int)(d * INV_SUBW);
                if (s > NSUB - 1) s = NSUB - 1;
                float cs = ((float)s + 0.5f) * SUBW;
                int mq = __float2int_rn((d - cs) * FIX);
                unsigned long long pk =
                    (1ull << 32) | (unsigned long long)(unsigned)(mq + MBIAS);
                atomicAdd(&s_pk[s], pk);
            }
        }
    }
    __syncthreads();

    // flush: one sub-bin per thread, skip empties; kernel boundary = global sync
    unsigned long long pv = s_pk[t];
    if (pv) atomicAdd(&g_pk[t], pv);
}

// =================== K2: reconstruction + finalize (1 block) ===================
__global__ void __launch_bounds__(TPB, 1)
rdf_finalize_kernel(float* __restrict__ out, int out_size) {
    __shared__ float s_nf[NSUB + 2 * PAD];
    __shared__ float s_mf[NSUB + 2 * PAD];
    __shared__ float s_cnt[NBINS];
    __shared__ float s_total;

    const int t = threadIdx.x;

    // FULL zeroing of guard-padded arrays (1216 > TPB: MUST be a strided loop;
    // the round-12 `if (t < ...)` left the upper guard as stale smem -> NaN)
    for (int k = t; k < NSUB + 2 * PAD; k += TPB) { s_nf[k] = 0.0f; s_mf[k] = 0.0f; }
    __syncthreads();
    {
        unsigned long long pv = g_pk[t];
        g_pk[t] = 0ull;                   // reset for next graph replay
        float n = (float)(unsigned)(pv >> 32);
        float m = ((float)(int)((unsigned)pv - (unsigned)(pv >> 32) * MBIAS)) * INV_FIX;
        s_nf[PAD + t] = n;
        s_mf[PAD + t] = m;
    }
    __syncthreads();

    // final bin k: 16 threads x 12 fixed-trip sub-bins; exp recurrence
    {
        const int k   = t >> 4;           // 0..63
        const int seg = t & 15;
        const float ck = (float)k * GW;
        const int s0 = __float2int_rn(ck * INV_SUBW) - 96 + seg * SEG_LEN;

        const float dlt = SUBW;
        float uu = ((float)s0 + 0.5f) * SUBW - ck;
        float e  = __expf(GCOEFF * uu * uu);
        float tt = __expf(GCOEFF * fmaf(2.0f * uu, dlt, dlt * dlt));
        const float q = __expf(2.0f * GCOEFF * dlt * dlt);

        float acc = 0.0f;
        #pragma unroll
        for (int ii = 0; ii < SEG_LEN; ++ii) {
            float n = s_nf[PAD + s0 + ii];
            float m = s_mf[PAD + s0 + ii];
            acc = fmaf(e, fmaf(2.0f * GCOEFF * uu, m, n), acc);  // n*f + m*f'
            e *= tt;
            tt *= q;
            uu += dlt;
        }
        acc += __shfl_xor_sync(0xffffffffu, acc, 1);
        acc += __shfl_xor_sync(0xffffffffu, acc, 2);
        acc += __shfl_xor_sync(0xffffffffu, acc, 4);
        acc += __shfl_xor_sync(0xffffffffu, acc, 8);
        if (seg == 0) s_cnt[k] = acc;
    }
    __syncthreads();
    if (t == 0) {
        float sum = 0.0f;
        for (int k = 0; k < NBINS; ++k) sum += s_cnt[k];
        s_total = sum;
    }
    __syncthreads();

    const float pi43 = 4.0f * 3.14159265358979f / 3.0f;
    const float num  = (2.0f * CUT_ADJ) * (2.0f * CUT_ADJ) * (2.0f * CUT_ADJ);
    if (out_size >= 2 * NBINS + 1) {
        // layout: BINS[65] then rdf[64]
        if (t <= NBINS) out[t] = (float)t * BIN_W;
        if (t < NBINS) {
            float b0 = (float)t * BIN_W;
            float b1 = (float)(t + 1) * BIN_W;
            float vol = pi43 * (b1 * b1 * b1 - b0 * b0 * b0);
            out[NBINS + 1 + t] = (s_cnt[t] / s_total) * num / (2.0f * vol);
        }
    } else {
        if (t < NBINS && t < out_size) {
            float b0 = (float)t * BIN_W;
            float b1 = (float)(t + 1) * BIN_W;
            float vol = pi43 * (b1 * b1 * b1 - b0 * b0 * b0);
            out[t] = (s_cnt[t] / s_total) * num / (2.0f * vol);
        }
    }
}

extern "C" void kernel_launch(void* const* d_in, const int* in_sizes, int n_in,
                              void* d_out, int out_size) {
    const float* xyz = (const float*)d_in[0];
    float* out = (float*)d_out;
    rdf_pairs_kernel<<<A_BLOCKS, TPB>>>(xyz);
    rdf_finalize_kernel<<<1, TPB>>>(out, out_size);
}